// round 1
// baseline (speedup 1.0000x reference)
#include <cuda_runtime.h>
#include <cstdint>

// Delta modulation encoder: x (64, 8, 131072) f32 -> spikes {-1,0,+1} f32.
// Flattened: 512 independent sequences of T=131072. thr = 0.1f.
//
// Parallel-over-T scheme: chunks of L=1024; each chunk is scanned from two
// bracketing guess states which bit-merge quickly (contraction); the merged
// suffix is exact independent of incoming state. A tiny sequential kernel
// chains exact incoming states across chunks; a fixup kernel rewrites the
// short pre-merge prefix of each chunk from the exact incoming state.
// Unmerged / out-of-bounds chunks fall back to exact serial recompute.

#define DM_L        1024
#define DM_T        131072
#define DM_NSEQ     512
#define DM_NCH_SEQ  (DM_T / DM_L)            /* 128  */
#define DM_NCHK     (DM_NSEQ * DM_NCH_SEQ)   /* 65536 */
#define DM_THR      0.1f
#define DM_GLO     (-2.8f)
#define DM_GHI      (2.8f)

__device__ float g_out[DM_NCHK];   // chunk outgoing state (guess trajectory)
__device__ int   g_mt [DM_NCHK];   // first bit-merge index (multiple of 8), or L
__device__ float g_in [DM_NCHK];   // exact incoming state (written by passB)
__device__ int   g_fix[DM_NCHK];   // prefix length to rewrite in pass2

__device__ __forceinline__ float dm_step(float x, float& r) {
    float e = x - r;
    float s = 0.0f;
    s = (e >  DM_THR) ?  1.0f : s;
    s = (e < -DM_THR) ? -1.0f : s;
    r = fmaf(s, DM_THR, r);   // s*thr exact; single round == reference FADD
    return s;
}

// ---------------------------------------------------------------------------
// Pass 1: one thread per chunk. Dual trajectories until the whole warp has
// bit-merged, then single trajectory. Writes spikes for the full chunk.
// ---------------------------------------------------------------------------
__global__ void __launch_bounds__(128) dm_pass1(const float* __restrict__ x,
                                                float* __restrict__ out) {
    const int id = blockIdx.x * 128 + threadIdx.x;   // grid sized exactly
    const size_t base = (size_t)id * DM_L;
    const float4* __restrict__ xv = reinterpret_cast<const float4*>(x + base);
    float4* __restrict__ ov = reinterpret_cast<float4*>(out + base);

    float rlo = DM_GLO, rhi = DM_GHI;
    int   mt = DM_L;
    bool  merged = false;
    int   t = 0;

    // ---- Phase A: dual trajectories (short: until warp-wide merge) ----
    while (t < DM_L) {
        float4 a = __ldcs(xv + (t >> 2));
        float4 b = __ldcs(xv + (t >> 2) + 1);
        float xs[8] = {a.x, a.y, a.z, a.w, b.x, b.y, b.z, b.w};
        float sp[8];
#pragma unroll
        for (int i = 0; i < 8; ++i) {
            dm_step(xs[i], rlo);
            sp[i] = dm_step(xs[i], rhi);
        }
        __stcs(ov + (t >> 2),     make_float4(sp[0], sp[1], sp[2], sp[3]));
        __stcs(ov + (t >> 2) + 1, make_float4(sp[4], sp[5], sp[6], sp[7]));
        t += 8;
        if (!merged) {
            merged = (__float_as_uint(rlo) == __float_as_uint(rhi));
            if (merged) mt = t;
        }
        if (__all_sync(0xFFFFFFFFu, merged)) break;
    }

    // ---- Phase B: single trajectory, 1-ahead prefetch ----
    float r = rhi;
    if (t < DM_L) {
        float4 c0 = __ldcs(xv + (t >> 2));
        float4 c1 = __ldcs(xv + (t >> 2) + 1);
        for (;;) {
            const int tn = t + 8;
            const bool more = tn < DM_L;
            float4 n0, n1;
            if (more) {
                n0 = __ldcs(xv + (tn >> 2));
                n1 = __ldcs(xv + (tn >> 2) + 1);
            }
            float xs[8] = {c0.x, c0.y, c0.z, c0.w, c1.x, c1.y, c1.z, c1.w};
            float sp[8];
#pragma unroll
            for (int i = 0; i < 8; ++i) sp[i] = dm_step(xs[i], r);
            __stcs(ov + (t >> 2),     make_float4(sp[0], sp[1], sp[2], sp[3]));
            __stcs(ov + (t >> 2) + 1, make_float4(sp[4], sp[5], sp[6], sp[7]));
            if (!more) break;
            c0 = n0; c1 = n1; t = tn;
        }
    }

    g_out[id] = r;
    g_mt[id]  = mt;
}

// ---------------------------------------------------------------------------
// Pass B: one thread per sequence. Chains exact incoming states across the
// 128 chunks. Trusted chunks cost O(1); otherwise exact serial fallback.
// Next chunk's record is prefetched off the dependency chain.
// ---------------------------------------------------------------------------
__global__ void dm_passB(const float* __restrict__ x) {
    const int seq = blockIdx.x * blockDim.x + threadIdx.x;
    if (seq >= DM_NSEQ) return;
    const int id0 = seq * DM_NCH_SEQ;

    float S = 0.0f;
    int   mt_c  = g_mt[id0];
    float out_c = g_out[id0];

    for (int j = 0; j < DM_NCH_SEQ; ++j) {
        const int id = id0 + j;
        int mt_n = 0; float out_n = 0.0f;
        if (j + 1 < DM_NCH_SEQ) {            // prefetch next record
            mt_n  = g_mt[id + 1];
            out_n = g_out[id + 1];
        }
        g_in[id] = S;
        const bool trust = (mt_c < DM_L) && (S >= DM_GLO) && (S <= DM_GHI);
        g_fix[id] = trust ? mt_c : DM_L;
        if (trust) {
            S = out_c;
        } else {
            // exact serial recompute of this chunk (rare insurance path)
            const float* __restrict__ xp = x + (size_t)id * DM_L;
#pragma unroll 4
            for (int tt = 0; tt < DM_L; ++tt) dm_step(xp[tt], S);
        }
        mt_c = mt_n; out_c = out_n;
    }
}

// ---------------------------------------------------------------------------
// Pass 2: rewrite the pre-merge prefix [0, fix) of each chunk from the exact
// incoming state. fix is a multiple of 8 (or L for fallback chunks).
// ---------------------------------------------------------------------------
__global__ void __launch_bounds__(128) dm_pass2(const float* __restrict__ x,
                                                float* __restrict__ out) {
    const int id = blockIdx.x * 128 + threadIdx.x;
    const int fix = g_fix[id];
    float r = g_in[id];
    const size_t base = (size_t)id * DM_L;
    const float4* __restrict__ xv = reinterpret_cast<const float4*>(x + base);
    float4* __restrict__ ov = reinterpret_cast<float4*>(out + base);

    for (int t = 0; t < fix; t += 8) {
        float4 a = __ldg(xv + (t >> 2));
        float4 b = __ldg(xv + (t >> 2) + 1);
        float xs[8] = {a.x, a.y, a.z, a.w, b.x, b.y, b.z, b.w};
        float sp[8];
#pragma unroll
        for (int i = 0; i < 8; ++i) sp[i] = dm_step(xs[i], r);
        __stcs(ov + (t >> 2),     make_float4(sp[0], sp[1], sp[2], sp[3]));
        __stcs(ov + (t >> 2) + 1, make_float4(sp[4], sp[5], sp[6], sp[7]));
    }
}

// ---------------------------------------------------------------------------
extern "C" void kernel_launch(void* const* d_in, const int* in_sizes, int n_in,
                              void* d_out, int out_size) {
    const float* x = (const float*)d_in[0];
    float* out = (float*)d_out;
    (void)in_sizes; (void)n_in; (void)out_size;

    dm_pass1<<<DM_NCHK / 128, 128>>>(x, out);
    dm_passB<<<1, DM_NSEQ>>>(x);
    dm_pass2<<<DM_NCHK / 128, 128>>>(x, out);
}

// round 3
// speedup vs baseline: 6.3186x; 6.3186x over previous
#include <cuda_runtime.h>
#include <cstdint>

// Delta modulation encoder: x (64, 8, 131072) f32 -> spikes {-1,0,+1} f32.
// 512 independent sequences of T=131072, thr = 0.1f.
//
// Exact speculative chunking:
//  pass1: per chunk (L=2048), warm up W=1024 steps from state 0 starting at
//         chunk_start-W (level contraction + ulp-capture puts the state on the
//         true orbit, usually BIT-EXACT). Record post-warm-up state g and
//         outgoing state o; write chunk spikes from g.
//  passB: per sequence (one block each, spread over SMs), chain the exact
//         state S. If S == g bitwise, chunk is provably exact: O(1) hop.
//         Else exact serial recompute (insurance) + flag for rewrite.
//  pass2: rewrite flagged chunks from their exact incoming state.
// Output is bit-exact vs reference in ALL cases.

#define DM_T        131072
#define DM_NSEQ     512
#define DM_L        2048
#define DM_W        1024
#define DM_NCH      (DM_T / DM_L)             /* 64    */
#define DM_NCHK     (DM_NSEQ * DM_NCH)        /* 32768 */
#define DM_THR      0.1f

__device__ float g_state[DM_NCHK];  // post-warm-up incoming state (speculative)
__device__ float g_out  [DM_NCHK];  // chunk outgoing state (speculative)
__device__ float g_in   [DM_NCHK];  // exact incoming state (passB)
__device__ int   g_fix  [DM_NCHK];  // 1 -> pass2 must rewrite this chunk

// One step, bitwise identical to reference:
//   e = x - r; spike = (e>thr) - (e<-thr); r += spike*thr.
// spike*thr is exact (+-0.1f or 0), so r update == r + copysign(thr,e) when
// |e|>thr. Chain: FADD -> {FSETP || LOP3} -> FSEL -> FADD  (~16 cy).
__device__ __forceinline__ float dm_step(float x, float& r) {
    float e = x - r;
    bool  p = fabsf(e) > DM_THR;
    float d = p ? copysignf(DM_THR, e) : 0.0f;
    r = r + d;
    return p ? copysignf(1.0f, e) : 0.0f;   // off the recurrence chain
}

// ---------------------------------------------------------------------------
// Pass 1: one thread per chunk. Warm-up (no output), then chunk body with
// spike output, 1-ahead prefetch on the streaming loads.
// ---------------------------------------------------------------------------
__global__ void __launch_bounds__(128) dm_pass1(const float* __restrict__ x,
                                                float* __restrict__ out) {
    const int id  = blockIdx.x * 128 + threadIdx.x;      // grid sized exactly
    const int seq = id / DM_NCH;
    const int c   = id % DM_NCH;
    const size_t sbase = (size_t)seq * DM_T;
    const size_t cbase = sbase + (size_t)c * DM_L;

    float r = 0.0f;

    // ---- warm-up: [cbase - W, cbase), discard spikes ----
    if (c > 0) {
        const float4* __restrict__ wv =
            reinterpret_cast<const float4*>(x + cbase - DM_W);
        float4 c0 = __ldg(wv + 0);
        float4 c1 = __ldg(wv + 1);
        for (int t = 0; t < DM_W; t += 8) {
            const int tn = t + 8;
            float4 n0, n1;
            if (tn < DM_W) { n0 = __ldg(wv + (tn >> 2)); n1 = __ldg(wv + (tn >> 2) + 1); }
            float xs[8] = {c0.x, c0.y, c0.z, c0.w, c1.x, c1.y, c1.z, c1.w};
#pragma unroll
            for (int i = 0; i < 8; ++i) dm_step(xs[i], r);
            c0 = n0; c1 = n1;
            if (tn >= DM_W) break;
        }
    }
    g_state[id] = r;   // speculative incoming state for this chunk

    // ---- chunk body: write spikes ----
    {
        const float4* __restrict__ xv = reinterpret_cast<const float4*>(x + cbase);
        float4*       __restrict__ ov = reinterpret_cast<float4*>(out + cbase);
        float4 c0 = __ldcs(xv + 0);
        float4 c1 = __ldcs(xv + 1);
        for (int t = 0; t < DM_L; t += 8) {
            const int tn = t + 8;
            float4 n0, n1;
            if (tn < DM_L) { n0 = __ldcs(xv + (tn >> 2)); n1 = __ldcs(xv + (tn >> 2) + 1); }
            float xs[8] = {c0.x, c0.y, c0.z, c0.w, c1.x, c1.y, c1.z, c1.w};
            float sp[8];
#pragma unroll
            for (int i = 0; i < 8; ++i) sp[i] = dm_step(xs[i], r);
            __stcs(ov + (t >> 2),     make_float4(sp[0], sp[1], sp[2], sp[3]));
            __stcs(ov + (t >> 2) + 1, make_float4(sp[4], sp[5], sp[6], sp[7]));
            c0 = n0; c1 = n1;
            if (tn >= DM_L) break;
        }
    }
    g_out[id] = r;
}

// ---------------------------------------------------------------------------
// Pass B: one block (32 threads) per sequence, 512 blocks spread over SMs.
// Lanes preload the 64 chunk records into shared memory; lane 0 walks them.
// Trusted chunk (S == g_state bitwise): O(1). Else exact serial recompute.
// ---------------------------------------------------------------------------
__global__ void __launch_bounds__(32) dm_passB(const float* __restrict__ x) {
    const int seq  = blockIdx.x;
    const int lane = threadIdx.x;
    const int id0  = seq * DM_NCH;

    __shared__ float s_state[DM_NCH];
    __shared__ float s_out  [DM_NCH];
    for (int j = lane; j < DM_NCH; j += 32) {
        s_state[j] = g_state[id0 + j];
        s_out  [j] = g_out  [id0 + j];
    }
    __syncwarp();

    if (lane == 0) {
        float S = 0.0f;
        for (int j = 0; j < DM_NCH; ++j) {
            const int id = id0 + j;
            g_in[id] = S;
            if (__float_as_uint(S) == __float_as_uint(s_state[j])) {
                g_fix[id] = 0;
                S = s_out[j];                 // provably exact
            } else {
                g_fix[id] = 1;                // exact serial recompute
                const float4* __restrict__ xv = reinterpret_cast<const float4*>(
                    x + (size_t)seq * DM_T + (size_t)j * DM_L);
#pragma unroll 2
                for (int t = 0; t < DM_L; t += 4) {
                    float4 a = __ldg(xv + (t >> 2));
                    dm_step(a.x, S); dm_step(a.y, S);
                    dm_step(a.z, S); dm_step(a.w, S);
                }
            }
        }
    }
}

// ---------------------------------------------------------------------------
// Pass 2: rewrite flagged chunks from their exact incoming state.
// ---------------------------------------------------------------------------
__global__ void __launch_bounds__(128) dm_pass2(const float* __restrict__ x,
                                                float* __restrict__ out) {
    const int id = blockIdx.x * 128 + threadIdx.x;
    if (!g_fix[id]) return;

    const int seq = id / DM_NCH;
    const int c   = id % DM_NCH;
    const size_t cbase = (size_t)seq * DM_T + (size_t)c * DM_L;
    const float4* __restrict__ xv = reinterpret_cast<const float4*>(x + cbase);
    float4*       __restrict__ ov = reinterpret_cast<float4*>(out + cbase);

    float r = g_in[id];
    float4 c0 = __ldg(xv + 0);
    float4 c1 = __ldg(xv + 1);
    for (int t = 0; t < DM_L; t += 8) {
        const int tn = t + 8;
        float4 n0, n1;
        if (tn < DM_L) { n0 = __ldg(xv + (tn >> 2)); n1 = __ldg(xv + (tn >> 2) + 1); }
        float xs[8] = {c0.x, c0.y, c0.z, c0.w, c1.x, c1.y, c1.z, c1.w};
        float sp[8];
#pragma unroll
        for (int i = 0; i < 8; ++i) sp[i] = dm_step(xs[i], r);
        __stcs(ov + (t >> 2),     make_float4(sp[0], sp[1], sp[2], sp[3]));
        __stcs(ov + (t >> 2) + 1, make_float4(sp[4], sp[5], sp[6], sp[7]));
        c0 = n0; c1 = n1;
        if (tn >= DM_L) break;
    }
}

// ---------------------------------------------------------------------------
extern "C" void kernel_launch(void* const* d_in, const int* in_sizes, int n_in,
                              void* d_out, int out_size) {
    const float* x = (const float*)d_in[0];
    float* out = (float*)d_out;
    (void)in_sizes; (void)n_in; (void)out_size;

    dm_pass1<<<DM_NCHK / 128, 128>>>(x, out);
    dm_passB<<<DM_NSEQ, 32>>>(x);
    dm_pass2<<<DM_NCHK / 128, 128>>>(x, out);
}

// round 4
// speedup vs baseline: 6.4070x; 1.0140x over previous
#include <cuda_runtime.h>
#include <cstdint>

// Delta modulation encoder: x (64, 8, 131072) f32 -> spikes {-1,0,+1} f32.
// 512 independent sequences of T=131072, thr = 0.1f.
//
// Exact speculative chunking:
//  pass1: per chunk (L=2048), warm up W=1024 steps from state 0 starting at
//         chunk_start-W (level contraction + ulp-capture puts the state on the
//         true orbit, usually BIT-EXACT). Record post-warm-up state g and
//         outgoing state o; write chunk spikes from g.
//  passB: per sequence (one block each, spread over SMs), chain the exact
//         state S. If S == g bitwise, chunk is provably exact: O(1) hop.
//         Else exact serial recompute (insurance) + flag for rewrite.
//  pass2: rewrite flagged chunks from their exact incoming state.
// Output is bit-exact vs reference in ALL cases.

#define DM_T        131072
#define DM_NSEQ     512
#define DM_L        2048
#define DM_W        1024
#define DM_NCH      (DM_T / DM_L)             /* 64    */
#define DM_NCHK     (DM_NSEQ * DM_NCH)        /* 32768 */
#define DM_THR      0.1f

__device__ float g_state[DM_NCHK];  // post-warm-up incoming state (speculative)
__device__ float g_out  [DM_NCHK];  // chunk outgoing state (speculative)
__device__ float g_in   [DM_NCHK];  // exact incoming state (passB)
__device__ int   g_fix  [DM_NCHK];  // 1 -> pass2 must rewrite this chunk

// One step, bitwise identical to reference:
//   e = x - r; spike = (e>thr) - (e<-thr); r += spike*thr.
// spike*thr is exact (+-0.1f or 0), so r update == r + copysign(thr,e) when
// |e|>thr. Chain: FADD -> {FSETP || LOP3} -> FSEL -> FADD  (~16 cy).
__device__ __forceinline__ float dm_step(float x, float& r) {
    float e = x - r;
    bool  p = fabsf(e) > DM_THR;
    float d = p ? copysignf(DM_THR, e) : 0.0f;
    r = r + d;
    return p ? copysignf(1.0f, e) : 0.0f;   // off the recurrence chain
}

// ---------------------------------------------------------------------------
// Pass 1: one thread per chunk. Warm-up (no output), then chunk body with
// spike output, 1-ahead prefetch on the streaming loads.
// ---------------------------------------------------------------------------
__global__ void __launch_bounds__(128) dm_pass1(const float* __restrict__ x,
                                                float* __restrict__ out) {
    const int id  = blockIdx.x * 128 + threadIdx.x;      // grid sized exactly
    const int seq = id / DM_NCH;
    const int c   = id % DM_NCH;
    const size_t sbase = (size_t)seq * DM_T;
    const size_t cbase = sbase + (size_t)c * DM_L;

    float r = 0.0f;

    // ---- warm-up: [cbase - W, cbase), discard spikes ----
    if (c > 0) {
        const float4* __restrict__ wv =
            reinterpret_cast<const float4*>(x + cbase - DM_W);
        float4 c0 = __ldg(wv + 0);
        float4 c1 = __ldg(wv + 1);
        for (int t = 0; t < DM_W; t += 8) {
            const int tn = t + 8;
            float4 n0, n1;
            if (tn < DM_W) { n0 = __ldg(wv + (tn >> 2)); n1 = __ldg(wv + (tn >> 2) + 1); }
            float xs[8] = {c0.x, c0.y, c0.z, c0.w, c1.x, c1.y, c1.z, c1.w};
#pragma unroll
            for (int i = 0; i < 8; ++i) dm_step(xs[i], r);
            c0 = n0; c1 = n1;
            if (tn >= DM_W) break;
        }
    }
    g_state[id] = r;   // speculative incoming state for this chunk

    // ---- chunk body: write spikes ----
    {
        const float4* __restrict__ xv = reinterpret_cast<const float4*>(x + cbase);
        float4*       __restrict__ ov = reinterpret_cast<float4*>(out + cbase);
        float4 c0 = __ldcs(xv + 0);
        float4 c1 = __ldcs(xv + 1);
        for (int t = 0; t < DM_L; t += 8) {
            const int tn = t + 8;
            float4 n0, n1;
            if (tn < DM_L) { n0 = __ldcs(xv + (tn >> 2)); n1 = __ldcs(xv + (tn >> 2) + 1); }
            float xs[8] = {c0.x, c0.y, c0.z, c0.w, c1.x, c1.y, c1.z, c1.w};
            float sp[8];
#pragma unroll
            for (int i = 0; i < 8; ++i) sp[i] = dm_step(xs[i], r);
            __stcs(ov + (t >> 2),     make_float4(sp[0], sp[1], sp[2], sp[3]));
            __stcs(ov + (t >> 2) + 1, make_float4(sp[4], sp[5], sp[6], sp[7]));
            c0 = n0; c1 = n1;
            if (tn >= DM_L) break;
        }
    }
    g_out[id] = r;
}

// ---------------------------------------------------------------------------
// Pass B: one block (32 threads) per sequence, 512 blocks spread over SMs.
// Lanes preload the 64 chunk records into shared memory; lane 0 walks them.
// Trusted chunk (S == g_state bitwise): O(1). Else exact serial recompute.
// ---------------------------------------------------------------------------
__global__ void __launch_bounds__(32) dm_passB(const float* __restrict__ x) {
    const int seq  = blockIdx.x;
    const int lane = threadIdx.x;
    const int id0  = seq * DM_NCH;

    __shared__ float s_state[DM_NCH];
    __shared__ float s_out  [DM_NCH];
    for (int j = lane; j < DM_NCH; j += 32) {
        s_state[j] = g_state[id0 + j];
        s_out  [j] = g_out  [id0 + j];
    }
    __syncwarp();

    if (lane == 0) {
        float S = 0.0f;
        for (int j = 0; j < DM_NCH; ++j) {
            const int id = id0 + j;
            g_in[id] = S;
            if (__float_as_uint(S) == __float_as_uint(s_state[j])) {
                g_fix[id] = 0;
                S = s_out[j];                 // provably exact
            } else {
                g_fix[id] = 1;                // exact serial recompute
                const float4* __restrict__ xv = reinterpret_cast<const float4*>(
                    x + (size_t)seq * DM_T + (size_t)j * DM_L);
#pragma unroll 2
                for (int t = 0; t < DM_L; t += 4) {
                    float4 a = __ldg(xv + (t >> 2));
                    dm_step(a.x, S); dm_step(a.y, S);
                    dm_step(a.z, S); dm_step(a.w, S);
                }
            }
        }
    }
}

// ---------------------------------------------------------------------------
// Pass 2: rewrite flagged chunks from their exact incoming state.
// ---------------------------------------------------------------------------
__global__ void __launch_bounds__(128) dm_pass2(const float* __restrict__ x,
                                                float* __restrict__ out) {
    const int id = blockIdx.x * 128 + threadIdx.x;
    if (!g_fix[id]) return;

    const int seq = id / DM_NCH;
    const int c   = id % DM_NCH;
    const size_t cbase = (size_t)seq * DM_T + (size_t)c * DM_L;
    const float4* __restrict__ xv = reinterpret_cast<const float4*>(x + cbase);
    float4*       __restrict__ ov = reinterpret_cast<float4*>(out + cbase);

    float r = g_in[id];
    float4 c0 = __ldg(xv + 0);
    float4 c1 = __ldg(xv + 1);
    for (int t = 0; t < DM_L; t += 8) {
        const int tn = t + 8;
        float4 n0, n1;
        if (tn < DM_L) { n0 = __ldg(xv + (tn >> 2)); n1 = __ldg(xv + (tn >> 2) + 1); }
        float xs[8] = {c0.x, c0.y, c0.z, c0.w, c1.x, c1.y, c1.z, c1.w};
        float sp[8];
#pragma unroll
        for (int i = 0; i < 8; ++i) sp[i] = dm_step(xs[i], r);
        __stcs(ov + (t >> 2),     make_float4(sp[0], sp[1], sp[2], sp[3]));
        __stcs(ov + (t >> 2) + 1, make_float4(sp[4], sp[5], sp[6], sp[7]));
        c0 = n0; c1 = n1;
        if (tn >= DM_L) break;
    }
}

// ---------------------------------------------------------------------------
extern "C" void kernel_launch(void* const* d_in, const int* in_sizes, int n_in,
                              void* d_out, int out_size) {
    const float* x = (const float*)d_in[0];
    float* out = (float*)d_out;
    (void)in_sizes; (void)n_in; (void)out_size;

    dm_pass1<<<DM_NCHK / 128, 128>>>(x, out);
    dm_passB<<<DM_NSEQ, 32>>>(x);
    dm_pass2<<<DM_NCHK / 128, 128>>>(x, out);
}

// round 5
// speedup vs baseline: 23.0754x; 3.6016x over previous
#include <cuda_runtime.h>
#include <cstdint>

// Delta modulation encoder: x (64, 8, 131072) f32 -> spikes {-1,0,+1} f32.
// 512 sequences of T=131072, thr = 0.1f. Output bit-exact vs reference.
//
// pass1:  parallel speculative pass (warm-up 512 steps). Writes spikes as
//         packed int8 words + per-128-step-block (state, margin) records.
// passB:  one exact chain per sequence. Per block: if recorded margin exceeds
//         |S - r0| + SLACK, all decisions provably match -> replay S from the
//         spike bytes (1 FFMA per step, 4 cy chain). Else exact recompute of
//         the 128 steps from x and rewrite of the spike bytes.
// decode: packed bytes -> float spikes, fully coalesced.

#define DM_T      131072
#define DM_NSEQ   512
#define DM_L      2048
#define DM_W      512
#define DM_NCH    (DM_T / DM_L)          /* 64    */
#define DM_NCHK   (DM_NSEQ * DM_NCH)     /* 32768 */
#define DM_B      128                    /* verification block   */
#define DM_NBS    (DM_T / DM_B)          /* 1024 blocks per seq  */
#define DM_THR    0.1f
#define DM_SLACK  1e-4f                  /* > 128*ulp(6) drift + sub rounding */

__device__ unsigned g_sd [DM_NSEQ * DM_T / 4];   // packed int8 spikes (64 MB)
__device__ float2   g_rec[DM_NSEQ * DM_NBS];     // (state@blockstart, margin)

// Reference step, bitwise: e = fl(x-r); pos=(e>thr); neg=(e<-thr);
// r = fl(r + spike*thr)  (spike*thr exact).
__device__ __forceinline__ unsigned dm_step_m(float xx, float& r, float& m) {
    float e = xx - r;
    bool pos = e >  DM_THR;
    bool neg = e < -DM_THR;
    r += pos ? DM_THR : (neg ? -DM_THR : 0.0f);
    m = fminf(m, fminf(fabsf(e - DM_THR), fabsf(e + DM_THR)));
    return pos ? 1u : (neg ? 0xFFu : 0u);
}
__device__ __forceinline__ unsigned dm_step_f(float xx, float& r) {
    float e = xx - r;
    bool pos = e >  DM_THR;
    bool neg = e < -DM_THR;
    r += pos ? DM_THR : (neg ? -DM_THR : 0.0f);
    return pos ? 1u : (neg ? 0xFFu : 0u);
}
__device__ __forceinline__ void dm_step_w(float xx, float& r) {
    float e = xx - r;
    bool pos = e >  DM_THR;
    bool neg = e < -DM_THR;
    r += pos ? DM_THR : (neg ? -DM_THR : 0.0f);
}

// ---------------------------------------------------------------------------
// Pass 1: one thread per 2048-chunk. Warm-up, then 16 blocks of 128 steps:
// emit packed spike bytes (uint4 = 16 spikes) and (state, margin) records.
// ---------------------------------------------------------------------------
__global__ void __launch_bounds__(128) dm_pass1(const float* __restrict__ x) {
    const int id  = blockIdx.x * 128 + threadIdx.x;      // grid sized exactly
    const int seq = id / DM_NCH;
    const int c   = id % DM_NCH;
    const size_t cbase = (size_t)seq * DM_T + (size_t)c * DM_L;

    float r = 0.0f;

    if (c > 0) {                                         // warm-up, no output
        const float4* __restrict__ wv =
            reinterpret_cast<const float4*>(x + cbase - DM_W);
#pragma unroll 4
        for (int g = 0; g < DM_W / 4; ++g) {
            float4 a = __ldg(wv + g);
            dm_step_w(a.x, r); dm_step_w(a.y, r);
            dm_step_w(a.z, r); dm_step_w(a.w, r);
        }
    }

    const float4* __restrict__ xv  = reinterpret_cast<const float4*>(x + cbase);
    uint4*        __restrict__ sdv = reinterpret_cast<uint4*>(g_sd) + cbase / 16;
    float2*       __restrict__ rp  = g_rec + cbase / DM_B;

    for (int b = 0; b < DM_L / DM_B; ++b) {              // 16 blocks
        float r0 = r, m = 1e30f;
#pragma unroll 2
        for (int g = 0; g < DM_B / 16; ++g) {            // 8 x 16 steps
            unsigned w[4];
#pragma unroll
            for (int q = 0; q < 4; ++q) {
                float4 a = __ldcs(xv + b * 32 + g * 4 + q);
                unsigned b0 = dm_step_m(a.x, r, m);
                unsigned b1 = dm_step_m(a.y, r, m);
                unsigned b2 = dm_step_m(a.z, r, m);
                unsigned b3 = dm_step_m(a.w, r, m);
                w[q] = b0 | (b1 << 8) | (b2 << 16) | (b3 << 24);
            }
            __stcs(sdv + b * 8 + g, make_uint4(w[0], w[1], w[2], w[3]));
        }
        rp[b] = make_float2(r0, m);
    }
}

// ---------------------------------------------------------------------------
// Pass B: one sequence per block (lane 0 active), 512 blocks over the SMs.
// Verified blocks: replay S from spike bytes (FFMA chain, 4 cy/step).
// Unverified: exact recompute from x + rewrite of spike bytes.
// ---------------------------------------------------------------------------
__global__ void __launch_bounds__(32) dm_passB(const float* __restrict__ x) {
    if (threadIdx.x != 0) return;
    const int seq = blockIdx.x;

    const uint4*  __restrict__ spv =
        reinterpret_cast<const uint4*>(g_sd) + (size_t)seq * (DM_T / 16);
    uint4*        __restrict__ spw =
        reinterpret_cast<uint4*>(g_sd) + (size_t)seq * (DM_T / 16);
    const float2* __restrict__ rec = g_rec + (size_t)seq * DM_NBS;

    float S = 0.0f;

    uint4 buf[8];
#pragma unroll
    for (int k = 0; k < 8; ++k) buf[k] = __ldg(spv + k);
    float2 rc = __ldg(rec + 0);

    for (int j = 0; j < DM_NBS; ++j) {
        // prefetch next block's bytes + record (independent of the chain)
        uint4 nbuf[8]; float2 nrc = rc;
        if (j + 1 < DM_NBS) {
#pragma unroll
            for (int k = 0; k < 8; ++k) nbuf[k] = __ldg(spv + (j + 1) * 8 + k);
            nrc = __ldg(rec + j + 1);
        }

        const float diff = fabsf(S - rc.x);
        if (rc.y > diff + DM_SLACK) {
            // provably exact replay: S += spike*thr, 128 serial FFMAs
#pragma unroll
            for (int k = 0; k < 8; ++k) {
                unsigned ws[4] = {buf[k].x, buf[k].y, buf[k].z, buf[k].w};
#pragma unroll
                for (int q = 0; q < 4; ++q) {
                    unsigned w = ws[q];
                    S += (float)(signed char)(w)       * DM_THR;
                    S += (float)(signed char)(w >> 8)  * DM_THR;
                    S += (float)(signed char)(w >> 16) * DM_THR;
                    S += (float)(signed char)(w >> 24) * DM_THR;
                }
            }
        } else {
            // exact recompute of this 128-step block; rewrite spike bytes
            const float4* __restrict__ xb = reinterpret_cast<const float4*>(
                x + (size_t)seq * DM_T + (size_t)j * DM_B);
#pragma unroll 2
            for (int g = 0; g < 8; ++g) {
                unsigned w[4];
#pragma unroll
                for (int q = 0; q < 4; ++q) {
                    float4 a = __ldg(xb + g * 4 + q);
                    unsigned b0 = dm_step_f(a.x, S);
                    unsigned b1 = dm_step_f(a.y, S);
                    unsigned b2 = dm_step_f(a.z, S);
                    unsigned b3 = dm_step_f(a.w, S);
                    w[q] = b0 | (b1 << 8) | (b2 << 16) | (b3 << 24);
                }
                spw[j * 8 + g] = make_uint4(w[0], w[1], w[2], w[3]);
            }
        }

#pragma unroll
        for (int k = 0; k < 8; ++k) buf[k] = nbuf[k];
        rc = nrc;
    }
}

// ---------------------------------------------------------------------------
// Decode: packed bytes -> float spikes. One uint32 word (4 spikes) per
// thread: coalesced 128B reads and 512B float4 writes per warp.
// ---------------------------------------------------------------------------
__global__ void __launch_bounds__(256) dm_decode(float* __restrict__ out) {
    const size_t i = (size_t)blockIdx.x * 256 + threadIdx.x;
    const unsigned w = g_sd[i];
    float4 f;
    f.x = (float)(signed char)(w);
    f.y = (float)(signed char)(w >> 8);
    f.z = (float)(signed char)(w >> 16);
    f.w = (float)(signed char)(w >> 24);
    reinterpret_cast<float4*>(out)[i] = f;
}

// ---------------------------------------------------------------------------
extern "C" void kernel_launch(void* const* d_in, const int* in_sizes, int n_in,
                              void* d_out, int out_size) {
    const float* x = (const float*)d_in[0];
    float* out = (float*)d_out;
    (void)in_sizes; (void)n_in; (void)out_size;

    dm_pass1 <<<DM_NCHK / 128, 128>>>(x);
    dm_passB <<<DM_NSEQ, 32>>>(x);
    dm_decode<<<(DM_NSEQ * DM_T / 4) / 256, 256>>>(out);
}